// round 15
// baseline (speedup 1.0000x reference)
#include <cuda_runtime.h>
#include <cuda_bf16.h>
#include <cstdint>

// DGCRM: after dead-code elimination, output = GRU cell over 16384 rows:
//   c = [h(64), x(2)]  (permuted combined vector, 66 wide)
//   z = sigmoid(c @ Wz + bz); r = sigmoid(c @ Wr + br)
//   cand = [r*h, x];  hc = tanh(cand @ Wc + bc)
//   out = z*h + (1-z)*hc
//
// R11 -> R12: all smem-weight variants saturate the per-SM smem crossbar
// (128 B/cyc) -> L1 ~45%, fma ~20%, ~30us. Weights now stream via
// ld.global.nc (L1-resident 50KB, own LSU port); smem holds only the
// transposed A tile (1 wavefront per j per warp). smem 17.4KB static,
// regs capped for 4 CTAs/SM -> ~16 warps/SM of latency hiding.

#define CIN 66
#define HIDD 64
#define RPB 32
#define TPB 128
#define ATS 33   // transposed A stride: odd -> conflict-free column reads

__device__ __align__(16) float g_Wf[3 * CIN * HIDD];  // [m][j][col], j in [h..,x] order
__device__ __align__(16) float g_Bf[3 * HIDD];

__device__ __forceinline__ unsigned long long pk2(float a, float b) {
    unsigned long long r;
    asm("mov.b64 %0, {%1, %2};" : "=l"(r) : "f"(a), "f"(b));
    return r;
}
__device__ __forceinline__ void upk2(unsigned long long v, float& a, float& b) {
    asm("mov.b64 {%0, %1}, %2;" : "=f"(a), "=f"(b) : "l"(v));
}
__device__ __forceinline__ void fma2(unsigned long long& d, unsigned long long a, unsigned long long b) {
    asm("fma.rn.f32x2 %0, %1, %2, %0;" : "+l"(d) : "l"(a), "l"(b));
}
// 16B weight fetch, guaranteed LDG.E.NC.128 (read-only, L1-cached).
__device__ __forceinline__ ulonglong2 ldg_u2(const float* p) {
    ulonglong2 u;
    asm("ld.global.nc.v2.u64 {%0, %1}, [%2];" : "=l"(u.x), "=l"(u.y) : "l"(p));
    return u;
}
__device__ __forceinline__ float fsig(float v) { return 1.f / (1.f + __expf(-v)); }
__device__ __forceinline__ float ftanh(float v) { return 1.f - 2.f / (__expf(2.f * v) + 1.f); }

// Fold rnn_W[6,198,64] -> 3 effective [66,64] matrices + biases, with row
// permutation (combined [x,h] order -> stored [h,x] order).
__global__ void fold_kernel(const float* __restrict__ W, const float* __restrict__ bvec) {
    int idx = blockIdx.x * blockDim.x + threadIdx.x;
    if (idx < 3 * CIN * HIDD) {
        int m = idx / (CIN * HIDD);
        int rem = idx - m * (CIN * HIDD);
        int j = rem / HIDD;
        int col = rem - j * HIDD;
        int k = (j < HIDD) ? (j + 2) : (j - HIDD);
        float s = 0.f;
#pragma unroll
        for (int t = 0; t < 2; ++t) {
            const float* base = W + (size_t)(2 * m + t) * 198 * HIDD + col;
            s += base[(size_t)k * HIDD]
               + 0.05f * (base[(size_t)(66 + k) * HIDD] + base[(size_t)(132 + k) * HIDD]);
        }
        g_Wf[idx] = s;
    }
    if (idx < 3 * HIDD) {
        int m = idx / HIDD, j = idx - m * HIDD;
        g_Bf[idx] = bvec[(2 * m) * HIDD + j] + bvec[(2 * m + 1) * HIDD + j];
    }
}

// Block: 32 rows, 4 warps. Warp w -> cols [16w,16w+16), lane -> row.
__global__ void __launch_bounds__(TPB, 4) dgcrm_main(
    const float* __restrict__ x, const float* __restrict__ h0,
    const float* __restrict__ Wg, const float* __restrict__ Bg,
    float* __restrict__ out)
{
    __shared__ float At[CIN * ATS];   // original [h,x], transposed
    __shared__ float Ac[CIN * ATS];   // candidate [r*h, x], transposed

    const int tid  = threadIdx.x;
    const int lane = tid & 31;
    const int c0   = (tid >> 5) * 16;
    const int g0   = blockIdx.x * RPB;

    // Stage A transposed: At[c][r], c = 0..63 from h, 64..65 from x.
#pragma unroll
    for (int it = 0; it < 4; ++it) {
        int i = tid + TPB * it;            // 0..511 = 32 rows x 16 quads
        int r = i >> 4, q = i & 15;
        float4 v = *(const float4*)(h0 + (size_t)(g0 + r) * HIDD + q * 4);
        At[(q * 4 + 0) * ATS + r] = v.x;
        At[(q * 4 + 1) * ATS + r] = v.y;
        At[(q * 4 + 2) * ATS + r] = v.z;
        At[(q * 4 + 3) * ATS + r] = v.w;
    }
    if (tid < RPB) {
        float2 v = *(const float2*)(x + (size_t)(g0 + tid) * 2);
        At[64 * ATS + tid] = v.x;  At[65 * ATS + tid] = v.y;
        Ac[64 * ATS + tid] = v.x;  Ac[65 * ATS + tid] = v.y;
    }
    __syncthreads();

    const float* Wz = Wg;
    const float* Wr = Wg + CIN * HIDD;
    const float* Wc = Wg + 2 * CIN * HIDD;

    unsigned long long zacc[8], racc[8];
#pragma unroll
    for (int i = 0; i < 8; ++i) { zacc[i] = 0ull; racc[i] = 0ull; }

    // ---- phase 1: z,r GEMMs. Weights via LDG.NC (L1), A via 1-wf LDS. ----
#pragma unroll 6
    for (int j = 0; j < CIN; ++j) {
        const float a = At[j * ATS + lane];
        const unsigned long long ap = pk2(a, a);
        const ulonglong2 z0 = ldg_u2(Wz + j * HIDD + c0);
        const ulonglong2 z1 = ldg_u2(Wz + j * HIDD + c0 + 4);
        const ulonglong2 r0 = ldg_u2(Wr + j * HIDD + c0);
        const ulonglong2 r1 = ldg_u2(Wr + j * HIDD + c0 + 4);
        fma2(zacc[0], ap, z0.x); fma2(zacc[1], ap, z0.y);
        fma2(zacc[2], ap, z1.x); fma2(zacc[3], ap, z1.y);
        fma2(racc[0], ap, r0.x); fma2(racc[1], ap, r0.y);
        fma2(racc[2], ap, r1.x); fma2(racc[3], ap, r1.y);
        const ulonglong2 z2 = ldg_u2(Wz + j * HIDD + c0 + 8);
        const ulonglong2 z3 = ldg_u2(Wz + j * HIDD + c0 + 12);
        const ulonglong2 r2 = ldg_u2(Wr + j * HIDD + c0 + 8);
        const ulonglong2 r3 = ldg_u2(Wr + j * HIDD + c0 + 12);
        fma2(zacc[4], ap, z2.x); fma2(zacc[5], ap, z2.y);
        fma2(zacc[6], ap, z3.x); fma2(zacc[7], ap, z3.y);
        fma2(racc[4], ap, r2.x); fma2(racc[5], ap, r2.y);
        fma2(racc[6], ap, r3.x); fma2(racc[7], ap, r3.y);
    }

    // ---- candidate: Ac[c][lane] = sigmoid(r + br) * h (warp-private cols,
    //      At untouched -> no sync needed before this) ----
#pragma unroll
    for (int i = 0; i < 8; ++i) {
        float r0, r1;
        upk2(racc[i], r0, r1);
        const int c = c0 + 2 * i;
        const float ha = At[c * ATS + lane];
        const float hb = At[(c + 1) * ATS + lane];
        Ac[c * ATS + lane]       = fsig(r0 + Bg[HIDD + c])     * ha;
        Ac[(c + 1) * ATS + lane] = fsig(r1 + Bg[HIDD + c + 1]) * hb;
    }
    __syncthreads();   // phase 2 reads all warps' candidate columns

    // ---- phase 2: hc GEMM over candidate ----
    unsigned long long cacc[8];
#pragma unroll
    for (int i = 0; i < 8; ++i) cacc[i] = 0ull;
#pragma unroll 6
    for (int j = 0; j < CIN; ++j) {
        const float a = Ac[j * ATS + lane];
        const unsigned long long ap = pk2(a, a);
        const ulonglong2 w0 = ldg_u2(Wc + j * HIDD + c0);
        const ulonglong2 w1 = ldg_u2(Wc + j * HIDD + c0 + 4);
        const ulonglong2 w2 = ldg_u2(Wc + j * HIDD + c0 + 8);
        const ulonglong2 w3 = ldg_u2(Wc + j * HIDD + c0 + 12);
        fma2(cacc[0], ap, w0.x); fma2(cacc[1], ap, w0.y);
        fma2(cacc[2], ap, w1.x); fma2(cacc[3], ap, w1.y);
        fma2(cacc[4], ap, w2.x); fma2(cacc[5], ap, w2.y);
        fma2(cacc[6], ap, w3.x); fma2(cacc[7], ap, w3.y);
    }

    // ---- epilogue: out = z*h + (1-z)*hc, 4x STG.128 per lane ----
    float ov[16];
#pragma unroll
    for (int i = 0; i < 8; ++i) {
        float za, zb, ca, cb;
        upk2(zacc[i], za, zb);
        upk2(cacc[i], ca, cb);
        const int c = c0 + 2 * i;
        za = fsig(za + Bg[c]);
        zb = fsig(zb + Bg[c + 1]);
        ca = ftanh(ca + Bg[2 * HIDD + c]);
        cb = ftanh(cb + Bg[2 * HIDD + c + 1]);
        const float ha = At[c * ATS + lane];
        const float hb = At[(c + 1) * ATS + lane];
        ov[2 * i]     = za * ha + (1.f - za) * ca;
        ov[2 * i + 1] = zb * hb + (1.f - zb) * cb;
    }
    float* orow = out + (size_t)(g0 + lane) * HIDD + c0;
#pragma unroll
    for (int q = 0; q < 4; ++q) {
        float4 o;
        o.x = ov[4 * q + 0]; o.y = ov[4 * q + 1];
        o.z = ov[4 * q + 2]; o.w = ov[4 * q + 3];
        *(float4*)(orow + 4 * q) = o;
    }
}

extern "C" void kernel_launch(void* const* d_in, const int* in_sizes, int n_in,
                              void* d_out, int out_size) {
    (void)in_sizes; (void)n_in; (void)out_size;
    const float* x    = (const float*)d_in[0];    // [16,1024,2]
    const float* h0   = (const float*)d_in[1];    // [16,1024,64]
    const float* rnnW = (const float*)d_in[12];   // [6,198,64]
    const float* rnnb = (const float*)d_in[13];   // [6,64]
    float* out = (float*)d_out;                   // [16,1024,64]

    void* wf_ptr = nullptr; void* bf_ptr = nullptr;
    cudaGetSymbolAddress(&wf_ptr, g_Wf);
    cudaGetSymbolAddress(&bf_ptr, g_Bf);

    fold_kernel<<<(3 * CIN * HIDD + 255) / 256, 256>>>(rnnW, rnnb);
    dgcrm_main<<<16384 / RPB, TPB>>>(x, h0, (const float*)wf_ptr,
                                     (const float*)bf_ptr, out);
}